// round 6
// baseline (speedup 1.0000x reference)
#include <cuda_runtime.h>
#include <cuda_bf16.h>
#include <math.h>

// Problem dims
#define SEQ    512
#define BATCH  128
#define INDIM  256
#define HID    512
#define ODIM   128
#define BH     (BATCH * HID)

// Recurrence decomposition: 8 batch groups x 16 hidden slices = 128 CTAs.
#define NG     8                    // batch groups
#define NS     16                   // hidden slices
#define BGR    16                   // rows per group (= warps per CTA)
#define NCR    32                   // cols per slice (= lanes)
#define KCH    32                   // k per warp
#define OC     8                    // out cols per CTA (128/16)
#define FST    520                  // per-(g,c) flag stream stride (ints)

// Scratch: xh written by K1, overwritten in-place by h_s (exchange medium).
__device__ float g_buf[(size_t)SEQ * BATCH * HID];
// W_hy transposed [col][k] so the fused epilogue reads k-contiguous.
__device__ float g_whyT[ODIM * HID];
// Single-writer flags: stream per (g,c), one int per step.
__device__ int g_flags[NG * NS * FST];

typedef unsigned long long ull;

__device__ __forceinline__ ull fma2(ull a, ull b, ull c) {
    ull d;
    asm("fma.rn.f32x2 %0, %1, %2, %3;" : "=l"(d) : "l"(a), "l"(b), "l"(c));
    return d;
}
__device__ __forceinline__ void upk(ull v, float& x, float& y) {
    asm("mov.b64 {%0,%1}, %2;" : "=f"(x), "=f"(y) : "l"(v));
}
__device__ __forceinline__ ull pk(float x, float y) {
    ull d;
    asm("mov.b64 %0, {%1,%2};" : "=l"(d) : "f"(x), "f"(y));
    return d;
}
__device__ __forceinline__ int ldacq(const int* p) {
    int v;
    asm volatile("ld.acquire.gpu.b32 %0, [%1];" : "=r"(v) : "l"(p));
    return v;
}
__device__ __forceinline__ void strel(int* p) {
    asm volatile("st.release.gpu.global.b32 [%0], %1;" :: "l"(p), "r"(1)
                 : "memory");
}

// ---------------------------------------------------------------------------
__global__ void zero_flags_kernel() {
    int i = blockIdx.x * blockDim.x + threadIdx.x;
    if (i < NG * NS * FST) g_flags[i] = 0;
}

// W_hy [512][128] -> g_whyT [128][512]
__global__ void transpose_why_kernel(const float* __restrict__ Why) {
    int i = blockIdx.x * blockDim.x + threadIdx.x;   // over 65536
    if (i < ODIM * HID) {
        int col = i >> 9;          // 0..127
        int k   = i & 511;         // 0..511
        g_whyT[i] = Why[(size_t)k * ODIM + col];
    }
}

// ---------------------------------------------------------------------------
// Tiled fp32 GEMM with bias: C[M,N] = A[M,K] @ B[K,N] + bias[N]  (xh pass)
// ---------------------------------------------------------------------------
template <int BM, int BN, int BK, int TM, int TN>
__global__ void __launch_bounds__(256, 2)
sgemm_bias_kernel(const float* __restrict__ A,
                  const float* __restrict__ B,
                  const float* __restrict__ bias,
                  float* __restrict__ C,
                  int M, int N, int K) {
    __shared__ float sA[BK][BM + 4];
    __shared__ float sB[BK][BN];

    const int tid = threadIdx.x;
    const int tx = tid % (BN / TN);
    const int ty = tid / (BN / TN);
    const int m0 = blockIdx.y * BM;
    const int n0 = blockIdx.x * BN;

    float acc[TM][TN];
#pragma unroll
    for (int i = 0; i < TM; i++)
#pragma unroll
        for (int j = 0; j < TN; j++) acc[i][j] = 0.0f;

    for (int k0 = 0; k0 < K; k0 += BK) {
#pragma unroll
        for (int i = 0; i < (BM * BK) / (256 * 4); ++i) {
            int idx = tid + i * 256;
            int r   = idx / (BK / 4);
            int kq  = (idx % (BK / 4)) * 4;
            float4 v = *(const float4*)&A[(size_t)(m0 + r) * K + k0 + kq];
            sA[kq + 0][r] = v.x;
            sA[kq + 1][r] = v.y;
            sA[kq + 2][r] = v.z;
            sA[kq + 3][r] = v.w;
        }
#pragma unroll
        for (int i = 0; i < (BK * BN) / (256 * 4); ++i) {
            int idx = tid + i * 256;
            int r   = idx / (BN / 4);
            int cq  = (idx % (BN / 4)) * 4;
            *(float4*)&sB[r][cq] =
                *(const float4*)&B[(size_t)(k0 + r) * N + n0 + cq];
        }
        __syncthreads();

#pragma unroll
        for (int kk = 0; kk < BK; ++kk) {
            float ra[TM], rb[TN];
#pragma unroll
            for (int i = 0; i < TM; i++) ra[i] = sA[kk][ty * TM + i];
#pragma unroll
            for (int j = 0; j < TN; j++) rb[j] = sB[kk][tx * TN + j];
#pragma unroll
            for (int i = 0; i < TM; i++)
#pragma unroll
                for (int j = 0; j < TN; j++) acc[i][j] += ra[i] * rb[j];
        }
        __syncthreads();
    }

#pragma unroll
    for (int i = 0; i < TM; i++) {
        int row = m0 + ty * TM + i;
#pragma unroll
        for (int j = 0; j < TN; j++) {
            int col = n0 + tx * TN + j;
            C[(size_t)row * N + col] = acc[i][j] + bias[col];
        }
    }
}

// ---------------------------------------------------------------------------
// Persistent recurrence kernel with per-warp producer matching + fused output.
// Grid: 128 CTAs = 8 groups x 16 slices, 512 threads (16 warps).
// CTA (g,c): rows [g*16,+16), cols [c*32,+32). Warp w: k-chunk [w*32,+32),
// whose producer is slice-CTA (g,w) -> warp w polls ONLY flag(g,w,s-1),
// stages ONLY its own 2KB h-block, computes its partial, then the CTA-wide
// reduce bar absorbs producer skew with compute already done.
// After publishing h[s], each CTA computes its out[s-1] tile (16r x 8c) from
// the fully-staged sHt in the next step's poll shadow (K3 eliminated).
// ---------------------------------------------------------------------------
#define REC_SMEM_BYTES ((BGR * HID + BGR * NS * NCR) * 4)   // 32KB + 32KB

__global__ void __launch_bounds__(512, 1)
rnn_recur_kernel(const float* __restrict__ Whh,
                 const float* __restrict__ by,
                 float* __restrict__ out) {
    extern __shared__ float sm[];
    float* sHt = sm;                     // [16 r][512 k]
    float* sRd = sm + BGR * HID;         // [16 r][16 ww][32 c]

    const int tid = threadIdx.x;
    const int w = tid >> 5;              // warp = k-chunk AND h-row AND out-row
    const int j = tid & 31;              // lane
    const int g = blockIdx.x >> 4;       // batch group 0..7
    const int c = blockIdx.x & 15;       // slice 0..15
    const int cb  = c * NCR;
    const int cb8 = c * OC;
    const int rowBase = g * BGR;
    const int K0 = w * KCH;

    // Preload W k-pairs: wp[p] = (W[K0+2p][cb+j], W[K0+2p+1][cb+j])
    ull wp[KCH / 2];
#pragma unroll
    for (int p = 0; p < KCH / 2; ++p) {
        float lo = Whh[(size_t)(K0 + 2 * p)     * HID + cb + j];
        float hi = Whh[(size_t)(K0 + 2 * p + 1) * HID + cb + j];
        wp[p] = pk(lo, hi);
    }

    // Fused-output mapping: lane -> (ocol, k-quarter)
    const int ocol = j >> 2;             // 0..7
    const int oq   = j & 3;              // 0..3
    const float byv = by[cb8 + ocol];
    const float* wyTp = g_whyT + (size_t)(cb8 + ocol) * HID + oq * 128;

    // h/xh mapping: (row, col) = (w, j)
    const size_t rowOffR = (size_t)(rowBase + w) * HID + cb + j;
    int* const myflag  = g_flags + (g * NS + c) * FST;
    const int* srcflag = g_flags + (g * NS + w) * FST;

    const int str = j >> 3;              // staging row phase 0..3
    const int stk = (j & 7) * 4;         // staging k offset

    float xh = __ldcg(&g_buf[rowOffR]);  // xh[0]

    for (int s = 0; s < SEQ; ++s) {
        float pf = 0.0f;
        if (s + 1 < SEQ)
            pf = __ldcg(&g_buf[(size_t)(s + 1) * BH + rowOffR]);

        float val = xh;
        if (s > 0) {
            // Per-warp wait on the one producer this warp depends on.
            while (ldacq(&srcflag[s - 1]) == 0) { }

            // Stage own block h[s-1][16 rows][K0..K0+32) (2 KB).
            const float* hb = g_buf + (size_t)(s - 1) * BH
                            + (size_t)rowBase * HID + K0;
#pragma unroll
            for (int i = 0; i < 4; ++i) {
                int r = str + i * 4;
                float4 v = __ldcg((const float4*)(hb + (size_t)r * HID + stk));
                *(float4*)&sHt[r * HID + K0 + stk] = v;
            }
            __syncthreads();

            // Partial dot: 16 rows x 1 col over this warp's 32 k.
            ull acc[BGR];
#pragma unroll
            for (int r = 0; r < BGR; ++r) acc[r] = 0;
#pragma unroll
            for (int t = 0; t < KCH / 4; ++t) {
                const int k = K0 + 4 * t;
#pragma unroll
                for (int r = 0; r < BGR; ++r) {
                    ulonglong2 h2 = *(const ulonglong2*)&sHt[r * HID + k];
                    acc[r] = fma2(h2.x, wp[2 * t],     acc[r]);
                    acc[r] = fma2(h2.y, wp[2 * t + 1], acc[r]);
                }
            }
#pragma unroll
            for (int r = 0; r < BGR; ++r) {
                float lo, hi;
                upk(acc[r], lo, hi);
                sRd[(r * NS + w) * NCR + j] = lo + hi;
            }
            __syncthreads();

            float sum = 0.0f;
#pragma unroll
            for (int ww = 0; ww < NS; ++ww)
                sum += sRd[(w * NS + ww) * NCR + j];
            val += sum;
        }

        float h = tanhf(val);
        g_buf[(size_t)s * BH + rowOffR] = h;

        __syncthreads();
        if (tid == 0) strel(&myflag[s]);

        // Fused out[s-1] (sHt holds h[s-1]) in the next poll's shadow.
        if (s > 0) {
            const float* hrow = &sHt[w * HID + oq * 128];
            float oacc = 0.0f;
#pragma unroll
            for (int t = 0; t < 32; ++t) {
                float4 hv = *(const float4*)&hrow[t * 4];
                float4 wv = __ldg((const float4*)&wyTp[t * 4]);
                oacc += hv.x * wv.x + hv.y * wv.y + hv.z * wv.z + hv.w * wv.w;
            }
            oacc += __shfl_xor_sync(0xFFFFFFFFu, oacc, 1);
            oacc += __shfl_xor_sync(0xFFFFFFFFu, oacc, 2);
            if (oq == 0)
                out[(size_t)(s - 1) * BATCH * ODIM
                    + (size_t)(rowBase + w) * ODIM + cb8 + ocol] = oacc + byv;
        }
        __syncthreads();      // protect sHt until all finished out[s-1]

        xh = pf;
    }

    // Epilogue: out[SEQ-1] (h[SEQ-1] never staged in-loop).
    while (ldacq(&srcflag[SEQ - 1]) == 0) { }
    {
        const float* hb = g_buf + (size_t)(SEQ - 1) * BH
                        + (size_t)rowBase * HID + K0;
#pragma unroll
        for (int i = 0; i < 4; ++i) {
            int r = str + i * 4;
            float4 v = __ldcg((const float4*)(hb + (size_t)r * HID + stk));
            *(float4*)&sHt[r * HID + K0 + stk] = v;
        }
        __syncthreads();

        const float* hrow = &sHt[w * HID + oq * 128];
        float oacc = 0.0f;
#pragma unroll
        for (int t = 0; t < 32; ++t) {
            float4 hv = *(const float4*)&hrow[t * 4];
            float4 wv = __ldg((const float4*)&wyTp[t * 4]);
            oacc += hv.x * wv.x + hv.y * wv.y + hv.z * wv.z + hv.w * wv.w;
        }
        oacc += __shfl_xor_sync(0xFFFFFFFFu, oacc, 1);
        oacc += __shfl_xor_sync(0xFFFFFFFFu, oacc, 2);
        if (oq == 0)
            out[(size_t)(SEQ - 1) * BATCH * ODIM
                + (size_t)(rowBase + w) * ODIM + cb8 + ocol] = oacc + byv;
    }
}

// ---------------------------------------------------------------------------
// kernel_launch
// Inputs: x[512,128,256], W_xh[256,512], W_hh[512,512],
//         W_hy[512,128], b_h[512], b_y[128]  -> out[512,128,128] fp32
// ---------------------------------------------------------------------------
extern "C" void kernel_launch(void* const* d_in, const int* in_sizes, int n_in,
                              void* d_out, int out_size) {
    const float* x   = (const float*)d_in[0];
    const float* Wxh = (const float*)d_in[1];
    const float* Whh = (const float*)d_in[2];
    const float* Why = (const float*)d_in[3];
    const float* bh  = (const float*)d_in[4];
    const float* by  = (const float*)d_in[5];
    float* out = (float*)d_out;

    float* buf = nullptr;
    cudaGetSymbolAddress((void**)&buf, g_buf);

    cudaFuncSetAttribute(rnn_recur_kernel,
                         cudaFuncAttributeMaxDynamicSharedMemorySize,
                         REC_SMEM_BYTES);

    // 0) zero flags + transpose W_hy (cheap setup)
    zero_flags_kernel<<<(NG * NS * FST + 255) / 256, 256>>>();
    transpose_why_kernel<<<(ODIM * HID + 255) / 256, 256>>>(Why);

    // 1) xh = x @ W_xh + b_h -> g_buf
    {
        dim3 grid(HID / 64, (SEQ * BATCH) / 128);
        sgemm_bias_kernel<128, 64, 16, 8, 4><<<grid, 256>>>(
            x, Wxh, bh, buf, SEQ * BATCH, HID, INDIM);
    }

    // 2) recurrence + fused output GEMM (K3 eliminated)
    rnn_recur_kernel<<<NG * NS, 512, REC_SMEM_BYTES>>>(Whh, by, out);
}

// round 8
// speedup vs baseline: 1.6430x; 1.6430x over previous
#include <cuda_runtime.h>
#include <cuda_bf16.h>
#include <math.h>

// Problem dims
#define SEQ    512
#define BATCH  128
#define INDIM  256
#define HID    512
#define ODIM   128
#define BH     (BATCH * HID)

// Recurrence decomposition: 8 batch groups x 16 hidden slices = 128 CTAs.
#define NG     8                    // batch groups
#define NS     16                   // hidden slices (producers per group flag)
#define BGR    16                   // rows per group (= warps per CTA)
#define NCR    32                   // cols per slice (= lanes)
#define KCH    32                   // k per warp (16 warps x 32 = 512)
#define OC     8                    // out cols per CTA (128/16)
#define FST    544                  // per-group flag stride (ints)

// Scratch: xh written by K1, overwritten in-place by h_s (exchange medium).
__device__ float g_buf[(size_t)SEQ * BATCH * HID];
// W_hy transposed [col][k] so the fused epilogue reads k-contiguous.
__device__ float g_whyT[ODIM * HID];
// Per-(group,step) completion counters, padded per group.
__device__ int g_flags[NG * FST];

typedef unsigned long long ull;

__device__ __forceinline__ ull fma2(ull a, ull b, ull c) {
    ull d;
    asm("fma.rn.f32x2 %0, %1, %2, %3;" : "=l"(d) : "l"(a), "l"(b), "l"(c));
    return d;
}
__device__ __forceinline__ void upk(ull v, float& x, float& y) {
    asm("mov.b64 {%0,%1}, %2;" : "=f"(x), "=f"(y) : "l"(v));
}
__device__ __forceinline__ ull pk(float x, float y) {
    ull d;
    asm("mov.b64 %0, {%1,%2};" : "=l"(d) : "f"(x), "f"(y));
    return d;
}
__device__ __forceinline__ int ldacq(const int* p) {
    int v;
    asm volatile("ld.acquire.gpu.b32 %0, [%1];" : "=r"(v) : "l"(p));
    return v;
}
__device__ __forceinline__ void red_release(int* p, int v) {
    asm volatile("red.release.gpu.global.add.s32 [%0], %1;" :: "l"(p), "r"(v)
                 : "memory");
}

// ---------------------------------------------------------------------------
__global__ void zero_flags_kernel() {
    int i = blockIdx.x * blockDim.x + threadIdx.x;
    if (i < NG * FST) g_flags[i] = 0;
}

// W_hy [512][128] -> g_whyT [128][512]
__global__ void transpose_why_kernel(const float* __restrict__ Why) {
    int i = blockIdx.x * blockDim.x + threadIdx.x;
    if (i < ODIM * HID) {
        int col = i >> 9;
        int k   = i & 511;
        g_whyT[i] = Why[(size_t)k * ODIM + col];
    }
}

// ---------------------------------------------------------------------------
// Tiled fp32 GEMM with bias (xh pass): C[M,N] = A[M,K] @ B[K,N] + bias[N]
// ---------------------------------------------------------------------------
template <int BM, int BN, int BK, int TM, int TN>
__global__ void __launch_bounds__(256, 2)
sgemm_bias_kernel(const float* __restrict__ A,
                  const float* __restrict__ B,
                  const float* __restrict__ bias,
                  float* __restrict__ C,
                  int M, int N, int K) {
    __shared__ float sA[BK][BM + 4];
    __shared__ float sB[BK][BN];

    const int tid = threadIdx.x;
    const int tx = tid % (BN / TN);
    const int ty = tid / (BN / TN);
    const int m0 = blockIdx.y * BM;
    const int n0 = blockIdx.x * BN;

    float acc[TM][TN];
#pragma unroll
    for (int i = 0; i < TM; i++)
#pragma unroll
        for (int j = 0; j < TN; j++) acc[i][j] = 0.0f;

    for (int k0 = 0; k0 < K; k0 += BK) {
#pragma unroll
        for (int i = 0; i < (BM * BK) / (256 * 4); ++i) {
            int idx = tid + i * 256;
            int r   = idx / (BK / 4);
            int kq  = (idx % (BK / 4)) * 4;
            float4 v = *(const float4*)&A[(size_t)(m0 + r) * K + k0 + kq];
            sA[kq + 0][r] = v.x;
            sA[kq + 1][r] = v.y;
            sA[kq + 2][r] = v.z;
            sA[kq + 3][r] = v.w;
        }
#pragma unroll
        for (int i = 0; i < (BK * BN) / (256 * 4); ++i) {
            int idx = tid + i * 256;
            int r   = idx / (BN / 4);
            int cq  = (idx % (BN / 4)) * 4;
            *(float4*)&sB[r][cq] =
                *(const float4*)&B[(size_t)(k0 + r) * N + n0 + cq];
        }
        __syncthreads();

#pragma unroll
        for (int kk = 0; kk < BK; ++kk) {
            float ra[TM], rb[TN];
#pragma unroll
            for (int i = 0; i < TM; i++) ra[i] = sA[kk][ty * TM + i];
#pragma unroll
            for (int j = 0; j < TN; j++) rb[j] = sB[kk][tx * TN + j];
#pragma unroll
            for (int i = 0; i < TM; i++)
#pragma unroll
                for (int j = 0; j < TN; j++) acc[i][j] += ra[i] * rb[j];
        }
        __syncthreads();
    }

#pragma unroll
    for (int i = 0; i < TM; i++) {
        int row = m0 + ty * TM + i;
#pragma unroll
        for (int j = 0; j < TN; j++) {
            int col = n0 + tx * TN + j;
            C[(size_t)row * N + col] = acc[i][j] + bias[col];
        }
    }
}

// ---------------------------------------------------------------------------
// Persistent recurrence kernel (R5-proven core) + fused output GEMM.
// Grid: 128 CTAs = 8 groups x 16 slices, 512 threads (16 warps).
// CTA (g,c): rows [g*16,+16), cols [c*32,+32). Warp w: k-chunk [w*32,+32).
// Lane j: column cb+j. W k-pairs pre-packed in registers (32 regs/thread).
// Exchange: per-group counter; red.release publish; single all-thread
// warp-uniform ld.acquire poll site per CTA.
// Fused out: after publishing h[s], sHt still holds h[s-1]; CTA computes
// its 16r x 8c out tile (warp=row; lane=(ocol, k-quarter); LDG.128 of
// L1-resident W_hy^T; shfl reduce). Standalone K3 pass eliminated.
// ---------------------------------------------------------------------------
#define REC_SMEM_BYTES ((BGR * HID + BGR * NS * NCR) * 4)   // 32KB + 32KB

__global__ void __launch_bounds__(512, 1)
rnn_recur_kernel(const float* __restrict__ Whh,
                 const float* __restrict__ by,
                 float* __restrict__ out) {
    extern __shared__ float sm[];
    float* sHt = sm;                     // [16 r][512 k]
    float* sRd = sm + BGR * HID;         // [16 r][16 ww][32 c]

    const int tid = threadIdx.x;
    const int w = tid >> 5;              // warp = k-chunk AND output row
    const int j = tid & 31;              // lane = column
    const int g = blockIdx.x >> 4;       // batch group 0..7
    const int c = blockIdx.x & 15;       // slice 0..15
    const int cb = c * NCR;
    const int rowBase = g * BGR;
    const int K0 = w * KCH;

    // Preload W k-pairs: wp[p] = (W[K0+2p][cb+j], W[K0+2p+1][cb+j])
    ull wp[KCH / 2];
#pragma unroll
    for (int p = 0; p < KCH / 2; ++p) {
        float lo = Whh[(size_t)(K0 + 2 * p)     * HID + cb + j];
        float hi = Whh[(size_t)(K0 + 2 * p + 1) * HID + cb + j];
        wp[p] = pk(lo, hi);
    }

    // h/xh mapping: (row, col) = (w, j).
    const size_t rowOffR = (size_t)(rowBase + w) * HID + cb + j;
    int* const flags = g_flags + g * FST;

    // Fused-output mapping: warp w -> out row w; lane -> (ocol, k-quarter).
    const int ocol = c * OC + (j >> 2);  // 8 cols per CTA
    const int oq   = j & 3;              // k-quarter [oq*128, +128)
    const float byv = by[ocol];
    const float* wyTp = g_whyT + (size_t)ocol * HID + oq * 128;

    float xh = __ldcg(&g_buf[rowOffR]);          // xh[0]

    for (int s = 0; s < SEQ; ++s) {
        float pf = 0.0f;
        if (s + 1 < SEQ)
            pf = __ldcg(&g_buf[(size_t)(s + 1) * BH + rowOffR]);

        float val = xh;
        if (s > 0) {
            // Single warp-uniform poll site per CTA.
            while (ldacq(&flags[s - 1]) < NS) { }

            // Stage h[s-1][16 rows][512 cols] -> sHt[r][k].
            const float4* src = (const float4*)
                (g_buf + (size_t)(s - 1) * BH + (size_t)rowBase * HID);
#pragma unroll
            for (int i = 0; i < 4; ++i) {
                int idx = tid + i * 512;          // 2048 float4 = 16x128
                ((float4*)sHt)[idx] = __ldcg(src + idx);
            }
            __syncthreads();

            // Partial dot over this warp's 32 k for 16 rows x 1 col.
            ull acc[BGR];
#pragma unroll
            for (int r = 0; r < BGR; ++r) acc[r] = 0;

#pragma unroll
            for (int t = 0; t < KCH / 4; ++t) {   // 4 k per iteration
                const int k = K0 + 4 * t;
#pragma unroll
                for (int r = 0; r < BGR; ++r) {
                    ulonglong2 h2 = *(const ulonglong2*)&sHt[r * HID + k];
                    acc[r] = fma2(h2.x, wp[2 * t],     acc[r]);
                    acc[r] = fma2(h2.y, wp[2 * t + 1], acc[r]);
                }
            }

            // Partials -> sRd[r][w][j] (lane-consecutive, conflict-free).
#pragma unroll
            for (int r = 0; r < BGR; ++r) {
                float lo, hi;
                upk(acc[r], lo, hi);
                sRd[(r * NS + w) * NCR + j] = lo + hi;
            }
            __syncthreads();

            // Reduce 16 k-chunk partials for (row=w, col=j).
            float sum = 0.0f;
#pragma unroll
            for (int ww = 0; ww < NS; ++ww)
                sum += sRd[(w * NS + ww) * NCR + j];
            val += sum;
        }

        float h = tanhf(val);
        g_buf[(size_t)s * BH + rowOffR] = h;      // coalesced per warp

        __syncthreads();
        if (tid == 0) red_release(&flags[s], 1);

        // Fused out[s-1]: sHt still holds h[s-1].
        if (s > 0) {
            const float* hrow = &sHt[w * HID + oq * 128];
            float oacc = 0.0f;
#pragma unroll
            for (int t = 0; t < 32; ++t) {
                float4 hv = *(const float4*)&hrow[t * 4];
                float4 wv = __ldg((const float4*)&wyTp[t * 4]);
                oacc += hv.x * wv.x + hv.y * wv.y + hv.z * wv.z + hv.w * wv.w;
            }
            oacc += __shfl_xor_sync(0xFFFFFFFFu, oacc, 1);
            oacc += __shfl_xor_sync(0xFFFFFFFFu, oacc, 2);
            if (oq == 0)
                out[(size_t)(s - 1) * BATCH * ODIM
                    + (size_t)(rowBase + w) * ODIM + ocol] = oacc + byv;
            __syncthreads();     // protect sHt until out[s-1] is done
        }

        xh = pf;
    }

    // Epilogue: out[SEQ-1] (h[SEQ-1] never staged in-loop).
    while (ldacq(&flags[SEQ - 1]) < NS) { }
    {
        const float4* src = (const float4*)
            (g_buf + (size_t)(SEQ - 1) * BH + (size_t)rowBase * HID);
#pragma unroll
        for (int i = 0; i < 4; ++i) {
            int idx = tid + i * 512;
            ((float4*)sHt)[idx] = __ldcg(src + idx);
        }
        __syncthreads();

        const float* hrow = &sHt[w * HID + oq * 128];
        float oacc = 0.0f;
#pragma unroll
        for (int t = 0; t < 32; ++t) {
            float4 hv = *(const float4*)&hrow[t * 4];
            float4 wv = __ldg((const float4*)&wyTp[t * 4]);
            oacc += hv.x * wv.x + hv.y * wv.y + hv.z * wv.z + hv.w * wv.w;
        }
        oacc += __shfl_xor_sync(0xFFFFFFFFu, oacc, 1);
        oacc += __shfl_xor_sync(0xFFFFFFFFu, oacc, 2);
        if (oq == 0)
            out[(size_t)(SEQ - 1) * BATCH * ODIM
                + (size_t)(rowBase + w) * ODIM + ocol] = oacc + byv;
    }
}

// ---------------------------------------------------------------------------
// kernel_launch
// Inputs: x[512,128,256], W_xh[256,512], W_hh[512,512],
//         W_hy[512,128], b_h[512], b_y[128]  -> out[512,128,128] fp32
// ---------------------------------------------------------------------------
extern "C" void kernel_launch(void* const* d_in, const int* in_sizes, int n_in,
                              void* d_out, int out_size) {
    const float* x   = (const float*)d_in[0];
    const float* Wxh = (const float*)d_in[1];
    const float* Whh = (const float*)d_in[2];
    const float* Why = (const float*)d_in[3];
    const float* bh  = (const float*)d_in[4];
    const float* by  = (const float*)d_in[5];
    float* out = (float*)d_out;

    float* buf = nullptr;
    cudaGetSymbolAddress((void**)&buf, g_buf);

    cudaFuncSetAttribute(rnn_recur_kernel,
                         cudaFuncAttributeMaxDynamicSharedMemorySize,
                         REC_SMEM_BYTES);

    // 0) setup: zero flags, transpose W_hy
    zero_flags_kernel<<<(NG * FST + 255) / 256, 256>>>();
    transpose_why_kernel<<<(ODIM * HID + 255) / 256, 256>>>(Why);

    // 1) xh = x @ W_xh + b_h -> g_buf
    {
        dim3 grid(HID / 64, (SEQ * BATCH) / 128);
        sgemm_bias_kernel<128, 64, 16, 8, 4><<<grid, 256>>>(
            x, Wxh, bh, buf, SEQ * BATCH, HID, INDIM);
    }

    // 2) recurrence + fused output GEMM (standalone K3 eliminated)
    rnn_recur_kernel<<<NG * NS, 512, REC_SMEM_BYTES>>>(Whh, by, out);
}

// round 9
// speedup vs baseline: 4.6934x; 2.8566x over previous
#include <cuda_runtime.h>
#include <cuda_bf16.h>
#include <math.h>

// Problem dims
#define SEQ    512
#define BATCH  128
#define INDIM  256
#define HID    512
#define ODIM   128
#define BH     (BATCH * HID)

// Recurrence: 16 batch groups of 8 rows; 16 hidden slices of 32 cols.
// 128 CTAs; CTA (q,c) runs TWO chains: group q (A) and group q+8 (B).
#define NG     16                   // batch groups (8 rows each)
#define NS     16                   // hidden slices = producers per group
#define BGR    8                    // rows per group
#define NCR    32                   // cols per slice (= lanes)
#define KCH    32                   // k per warp (16 warps x 32 = 512)
#define FST    544                  // per-group flag stride (ints)

// Scratch: xh written by K1, overwritten in-place by h_s, consumed by K3.
__device__ float g_buf[(size_t)SEQ * BATCH * HID];
// Per-(group,step) completion counters, padded per group.
__device__ int g_flags[NG * FST];

typedef unsigned long long ull;

__device__ __forceinline__ ull fma2(ull a, ull b, ull c) {
    ull d;
    asm("fma.rn.f32x2 %0, %1, %2, %3;" : "=l"(d) : "l"(a), "l"(b), "l"(c));
    return d;
}
__device__ __forceinline__ void upk(ull v, float& x, float& y) {
    asm("mov.b64 {%0,%1}, %2;" : "=f"(x), "=f"(y) : "l"(v));
}
__device__ __forceinline__ ull pk(float x, float y) {
    ull d;
    asm("mov.b64 %0, {%1,%2};" : "=l"(d) : "f"(x), "f"(y));
    return d;
}
__device__ __forceinline__ int ldacq(const int* p) {
    int v;
    asm volatile("ld.acquire.gpu.b32 %0, [%1];" : "=r"(v) : "l"(p));
    return v;
}
__device__ __forceinline__ void red_release(int* p, int v) {
    asm volatile("red.release.gpu.global.add.s32 [%0], %1;" :: "l"(p), "r"(v)
                 : "memory");
}

// ---------------------------------------------------------------------------
__global__ void zero_flags_kernel() {
    int i = blockIdx.x * blockDim.x + threadIdx.x;
    if (i < NG * FST) g_flags[i] = 0;
}

// ---------------------------------------------------------------------------
// Tiled fp32 GEMM with bias: C[M,N] = A[M,K] @ B[K,N] + bias[N]
// ---------------------------------------------------------------------------
template <int BM, int BN, int BK, int TM, int TN>
__global__ void __launch_bounds__(256, 2)
sgemm_bias_kernel(const float* __restrict__ A,
                  const float* __restrict__ B,
                  const float* __restrict__ bias,
                  float* __restrict__ C,
                  int M, int N, int K) {
    __shared__ float sA[BK][BM + 4];
    __shared__ float sB[BK][BN];

    const int tid = threadIdx.x;
    const int tx = tid % (BN / TN);
    const int ty = tid / (BN / TN);
    const int m0 = blockIdx.y * BM;
    const int n0 = blockIdx.x * BN;

    float acc[TM][TN];
#pragma unroll
    for (int i = 0; i < TM; i++)
#pragma unroll
        for (int j = 0; j < TN; j++) acc[i][j] = 0.0f;

    for (int k0 = 0; k0 < K; k0 += BK) {
#pragma unroll
        for (int i = 0; i < (BM * BK) / (256 * 4); ++i) {
            int idx = tid + i * 256;
            int r   = idx / (BK / 4);
            int kq  = (idx % (BK / 4)) * 4;
            float4 v = *(const float4*)&A[(size_t)(m0 + r) * K + k0 + kq];
            sA[kq + 0][r] = v.x;
            sA[kq + 1][r] = v.y;
            sA[kq + 2][r] = v.z;
            sA[kq + 3][r] = v.w;
        }
#pragma unroll
        for (int i = 0; i < (BK * BN) / (256 * 4); ++i) {
            int idx = tid + i * 256;
            int r   = idx / (BN / 4);
            int cq  = (idx % (BN / 4)) * 4;
            *(float4*)&sB[r][cq] =
                *(const float4*)&B[(size_t)(k0 + r) * N + n0 + cq];
        }
        __syncthreads();

#pragma unroll
        for (int kk = 0; kk < BK; ++kk) {
            float ra[TM], rb[TN];
#pragma unroll
            for (int i = 0; i < TM; i++) ra[i] = sA[kk][ty * TM + i];
#pragma unroll
            for (int j = 0; j < TN; j++) rb[j] = sB[kk][tx * TN + j];
#pragma unroll
            for (int i = 0; i < TM; i++)
#pragma unroll
                for (int j = 0; j < TN; j++) acc[i][j] += ra[i] * rb[j];
        }
        __syncthreads();
    }

#pragma unroll
    for (int i = 0; i < TM; i++) {
        int row = m0 + ty * TM + i;
#pragma unroll
        for (int j = 0; j < TN; j++) {
            int col = n0 + tx * TN + j;
            C[(size_t)row * N + col] = acc[i][j] + bias[col];
        }
    }
}

// ---------------------------------------------------------------------------
// Persistent recurrence kernel — TWO interleaved chains per CTA.
// Grid: 128 CTAs = 8 pair-slots(q) x 16 slices(c), 512 threads (16 warps).
// CTA (q,c): chain A = group q, chain B = group q+8; cols [c*32,+32);
// warp w = k-chunk [w*32,+32). W k-pairs in registers (shared by chains).
// Within one iteration: pollA / stageA / dotA / reduceA / publishA, then
// the same for B. By the time the CTA returns to pollA(s+1), all peers
// published A(s) a full B-phase earlier -> poll passes immediately, hiding
// the L2 exchange latency that dominated R5's step time.
// Exchange: per-group counter, red.release publish, single warp-uniform
// ld.acquire poll site (the R5-proven pattern).
// ---------------------------------------------------------------------------
#define REC_SMEM_BYTES ((2 * BGR * HID + 2 * BGR * NS * NCR) * 4)  // 64 KB

__global__ void __launch_bounds__(512, 1)
rnn_recur_kernel(const float* __restrict__ Whh) {
    extern __shared__ float sm[];
    float* sHtA = sm;                          // [8 r][512 k]
    float* sHtB = sm + BGR * HID;              // [8 r][512 k]
    float* sRdA = sm + 2 * BGR * HID;          // [8 r][16 ww][32 c]
    float* sRdB = sRdA + BGR * NS * NCR;       // [8 r][16 ww][32 c]

    const int tid = threadIdx.x;
    const int w = tid >> 5;               // warp = k-chunk id (and row id w<8)
    const int j = tid & 31;               // lane = column
    const int q = blockIdx.x >> 4;        // pair slot 0..7
    const int c = blockIdx.x & 15;        // slice 0..15
    const int cb = c * NCR;
    const int gA = q, gB = q + 8;
    const int rbA = gA * BGR, rbB = gB * BGR;
    const int K0 = w * KCH;

    // Preload W k-pairs: wp[p] = (W[K0+2p][cb+j], W[K0+2p+1][cb+j])
    ull wp[KCH / 2];
#pragma unroll
    for (int p = 0; p < KCH / 2; ++p) {
        float lo = Whh[(size_t)(K0 + 2 * p)     * HID + cb + j];
        float hi = Whh[(size_t)(K0 + 2 * p + 1) * HID + cb + j];
        wp[p] = pk(lo, hi);
    }

    // Final-value mapping (w < 8): row rb+w, col cb+j.
    const size_t rowOffA = (size_t)(rbA + w) * HID + cb + j;
    const size_t rowOffB = (size_t)(rbB + w) * HID + cb + j;
    int* const flagsA = g_flags + gA * FST;
    int* const flagsB = g_flags + gB * FST;

    float xhA = 0.0f, xhB = 0.0f;
    if (w < 8) {
        xhA = __ldcg(&g_buf[rowOffA]);
        xhB = __ldcg(&g_buf[rowOffB]);
    }

    for (int s = 0; s < SEQ; ++s) {
        // Prefetch next step's xh for both chains (hidden under this step).
        float pfA = 0.0f, pfB = 0.0f;
        if (w < 8 && s + 1 < SEQ) {
            pfA = __ldcg(&g_buf[(size_t)(s + 1) * BH + rowOffA]);
            pfB = __ldcg(&g_buf[(size_t)(s + 1) * BH + rowOffB]);
        }

        // ================= chain A =================
        {
            float va = xhA;
            if (s > 0) {
                while (ldacq(&flagsA[s - 1]) < NS) { }

                const float4* src = (const float4*)
                    (g_buf + (size_t)(s - 1) * BH + (size_t)rbA * HID);
                ((float4*)sHtA)[tid]       = __ldcg(src + tid);
                ((float4*)sHtA)[tid + 512] = __ldcg(src + tid + 512);
                __syncthreads();

                ull acc[BGR];
#pragma unroll
                for (int r = 0; r < BGR; ++r) acc[r] = 0;
#pragma unroll
                for (int t = 0; t < KCH / 4; ++t) {
                    const int k = K0 + 4 * t;
#pragma unroll
                    for (int r = 0; r < BGR; ++r) {
                        ulonglong2 h2 = *(const ulonglong2*)&sHtA[r * HID + k];
                        acc[r] = fma2(h2.x, wp[2 * t],     acc[r]);
                        acc[r] = fma2(h2.y, wp[2 * t + 1], acc[r]);
                    }
                }
#pragma unroll
                for (int r = 0; r < BGR; ++r) {
                    float lo, hi;
                    upk(acc[r], lo, hi);
                    sRdA[(r * NS + w) * NCR + j] = lo + hi;
                }
                __syncthreads();

                if (w < 8) {
                    float sum = 0.0f;
#pragma unroll
                    for (int ww = 0; ww < NS; ++ww)
                        sum += sRdA[(w * NS + ww) * NCR + j];
                    va += sum;
                }
            }
            if (w < 8)
                g_buf[(size_t)s * BH + rowOffA] = tanhf(va);
            __syncthreads();
            if (tid == 0) red_release(&flagsA[s], 1);
        }

        // ================= chain B =================
        {
            float vb = xhB;
            if (s > 0) {
                while (ldacq(&flagsB[s - 1]) < NS) { }

                const float4* src = (const float4*)
                    (g_buf + (size_t)(s - 1) * BH + (size_t)rbB * HID);
                ((float4*)sHtB)[tid]       = __ldcg(src + tid);
                ((float4*)sHtB)[tid + 512] = __ldcg(src + tid + 512);
                __syncthreads();

                ull acc[BGR];
#pragma unroll
                for (int r = 0; r < BGR; ++r) acc[r] = 0;
#pragma unroll
                for (int t = 0; t < KCH / 4; ++t) {
                    const int k = K0 + 4 * t;
#pragma unroll
                    for (int r = 0; r < BGR; ++r) {
                        ulonglong2 h2 = *(const ulonglong2*)&sHtB[r * HID + k];
                        acc[r] = fma2(h2.x, wp[2 * t],     acc[r]);
                        acc[r] = fma2(h2.y, wp[2 * t + 1], acc[r]);
                    }
                }
#pragma unroll
                for (int r = 0; r < BGR; ++r) {
                    float lo, hi;
                    upk(acc[r], lo, hi);
                    sRdB[(r * NS + w) * NCR + j] = lo + hi;
                }
                __syncthreads();

                if (w < 8) {
                    float sum = 0.0f;
#pragma unroll
                    for (int ww = 0; ww < NS; ++ww)
                        sum += sRdB[(w * NS + ww) * NCR + j];
                    vb += sum;
                }
            }
            if (w < 8)
                g_buf[(size_t)s * BH + rowOffB] = tanhf(vb);
            __syncthreads();
            if (tid == 0) red_release(&flagsB[s], 1);
        }

        xhA = pfA;
        xhB = pfB;
    }
}

// ---------------------------------------------------------------------------
// kernel_launch
// Inputs: x[512,128,256], W_xh[256,512], W_hh[512,512],
//         W_hy[512,128], b_h[512], b_y[128]  -> out[512,128,128] fp32
// ---------------------------------------------------------------------------
extern "C" void kernel_launch(void* const* d_in, const int* in_sizes, int n_in,
                              void* d_out, int out_size) {
    const float* x   = (const float*)d_in[0];
    const float* Wxh = (const float*)d_in[1];
    const float* Whh = (const float*)d_in[2];
    const float* Why = (const float*)d_in[3];
    const float* bh  = (const float*)d_in[4];
    const float* by  = (const float*)d_in[5];
    float* out = (float*)d_out;

    float* buf = nullptr;
    cudaGetSymbolAddress((void**)&buf, g_buf);

    cudaFuncSetAttribute(rnn_recur_kernel,
                         cudaFuncAttributeMaxDynamicSharedMemorySize,
                         REC_SMEM_BYTES);

    // 0) zero the per-step flags (deterministic per graph replay)
    zero_flags_kernel<<<(NG * FST + 255) / 256, 256>>>();

    // 1) xh = x @ W_xh + b_h -> g_buf
    {
        dim3 grid(HID / 64, (SEQ * BATCH) / 128);
        sgemm_bias_kernel<128, 64, 16, 8, 4><<<grid, 256>>>(
            x, Wxh, bh, buf, SEQ * BATCH, HID, INDIM);
    }

    // 2) recurrence (two interleaved chains per CTA)
    rnn_recur_kernel<<<128, 512, REC_SMEM_BYTES>>>(Whh);

    // 3) out = hs @ W_hy + b_y
    {
        dim3 grid(ODIM / 64, (SEQ * BATCH) / 128);
        sgemm_bias_kernel<128, 64, 16, 8, 4><<<grid, 256>>>(
            buf, Why, by, out, SEQ * BATCH, ODIM, HID);
    }
}

// round 10
// speedup vs baseline: 5.5096x; 1.1739x over previous
#include <cuda_runtime.h>
#include <cuda_bf16.h>
#include <math.h>

// Problem dims
#define SEQ    512
#define BATCH  128
#define INDIM  256
#define HID    512
#define ODIM   128
#define BH     (BATCH * HID)

// Recurrence: 16 batch groups of 8 rows; 16 hidden slices of 32 cols.
// 128 CTAs; CTA (q,c) runs TWO interleaved chains: group q (A), q+8 (B).
#define NG     16                   // batch groups (8 rows each)
#define BGR    8                    // rows per group
#define NCR    32                   // cols per slice (= lanes)
#define KCH    32                   // k per warp (16 warps x 32 = 512)
#define NPROD  128                  // producers per group flag: 16 CTAs x 8 warps
#define FST    544                  // per-group flag stride (ints)

__device__ float g_buf[(size_t)SEQ * BATCH * HID];
__device__ int g_flags[NG * FST];

typedef unsigned long long ull;

__device__ __forceinline__ ull fma2(ull a, ull b, ull c) {
    ull d;
    asm("fma.rn.f32x2 %0, %1, %2, %3;" : "=l"(d) : "l"(a), "l"(b), "l"(c));
    return d;
}
__device__ __forceinline__ void upk(ull v, float& x, float& y) {
    asm("mov.b64 {%0,%1}, %2;" : "=f"(x), "=f"(y) : "l"(v));
}
__device__ __forceinline__ ull pk(float x, float y) {
    ull d;
    asm("mov.b64 %0, {%1,%2};" : "=l"(d) : "f"(x), "f"(y));
    return d;
}
__device__ __forceinline__ int ldacq(const int* p) {
    int v;
    asm volatile("ld.acquire.gpu.b32 %0, [%1];" : "=r"(v) : "l"(p));
    return v;
}
__device__ __forceinline__ void red_release(int* p, int v) {
    asm volatile("red.release.gpu.global.add.s32 [%0], %1;" :: "l"(p), "r"(v)
                 : "memory");
}

// ---------------------------------------------------------------------------
__global__ void zero_flags_kernel() {
    int i = blockIdx.x * blockDim.x + threadIdx.x;
    if (i < NG * FST) g_flags[i] = 0;
}

// ---------------------------------------------------------------------------
// Tiled fp32 GEMM with bias: C[M,N] = A[M,K] @ B[K,N] + bias[N]
// ---------------------------------------------------------------------------
template <int BM, int BN, int BK, int TM, int TN>
__global__ void __launch_bounds__(256, 2)
sgemm_bias_kernel(const float* __restrict__ A,
                  const float* __restrict__ B,
                  const float* __restrict__ bias,
                  float* __restrict__ C,
                  int M, int N, int K) {
    __shared__ float sA[BK][BM + 4];
    __shared__ float sB[BK][BN];

    const int tid = threadIdx.x;
    const int tx = tid % (BN / TN);
    const int ty = tid / (BN / TN);
    const int m0 = blockIdx.y * BM;
    const int n0 = blockIdx.x * BN;

    float acc[TM][TN];
#pragma unroll
    for (int i = 0; i < TM; i++)
#pragma unroll
        for (int j = 0; j < TN; j++) acc[i][j] = 0.0f;

    for (int k0 = 0; k0 < K; k0 += BK) {
#pragma unroll
        for (int i = 0; i < (BM * BK) / (256 * 4); ++i) {
            int idx = tid + i * 256;
            int r   = idx / (BK / 4);
            int kq  = (idx % (BK / 4)) * 4;
            float4 v = *(const float4*)&A[(size_t)(m0 + r) * K + k0 + kq];
            sA[kq + 0][r] = v.x;
            sA[kq + 1][r] = v.y;
            sA[kq + 2][r] = v.z;
            sA[kq + 3][r] = v.w;
        }
#pragma unroll
        for (int i = 0; i < (BK * BN) / (256 * 4); ++i) {
            int idx = tid + i * 256;
            int r   = idx / (BN / 4);
            int cq  = (idx % (BN / 4)) * 4;
            *(float4*)&sB[r][cq] =
                *(const float4*)&B[(size_t)(k0 + r) * N + n0 + cq];
        }
        __syncthreads();

#pragma unroll
        for (int kk = 0; kk < BK; ++kk) {
            float ra[TM], rb[TN];
#pragma unroll
            for (int i = 0; i < TM; i++) ra[i] = sA[kk][ty * TM + i];
#pragma unroll
            for (int j = 0; j < TN; j++) rb[j] = sB[kk][tx * TN + j];
#pragma unroll
            for (int i = 0; i < TM; i++)
#pragma unroll
                for (int j = 0; j < TN; j++) acc[i][j] += ra[i] * rb[j];
        }
        __syncthreads();
    }

#pragma unroll
    for (int i = 0; i < TM; i++) {
        int row = m0 + ty * TM + i;
#pragma unroll
        for (int j = 0; j < TN; j++) {
            int col = n0 + tx * TN + j;
            C[(size_t)row * N + col] = acc[i][j] + bias[col];
        }
    }
}

// ---------------------------------------------------------------------------
// Persistent recurrence, two interleaved chains, per-warp stage & publish.
// Grid: 128 CTAs = 8 pair-slots(q) x 16 slices(c), 512 threads (16 warps).
// Chain A = group q, chain B = group q+8; CTA cols [c*32,+32).
// Warp w: k-chunk [w*32,+32), private sHt region (8 rows x 32 k, XOR-swizzled)
// staged by the warp itself (LDG->STS, __syncwarp only). Dot: broadcast
// LDS.128 + packed FFMA2 with W in registers. ONE CTA barrier per phase
// (before the cross-warp k-reduce). Producing warps (w<8) publish h rows
// individually: STG + __syncwarp + lane0 red.release; group counter target
// NPROD=128. Consumers poll with a single warp-uniform ld.acquire.
// ---------------------------------------------------------------------------
#define SHT_W   256                           // floats per warp region
#define SRD_SZ  (BGR * 16 * NCR)              // 4096 floats
#define REC_SMEM_BYTES ((2 * 16 * SHT_W + 2 * SRD_SZ) * 4)   // 64 KB

__global__ void __launch_bounds__(512, 1)
rnn_recur_kernel(const float* __restrict__ Whh) {
    extern __shared__ float sm[];
    float* sHtA = sm;                          // [16 w][256]
    float* sHtB = sm + 16 * SHT_W;
    float* sRdA = sm + 2 * 16 * SHT_W;         // [8 r][16 ww][32 j]
    float* sRdB = sRdA + SRD_SZ;

    const int tid = threadIdx.x;
    const int w = tid >> 5;               // warp = k-chunk id (row id if w<8)
    const int j = tid & 31;               // lane = column
    const int q = blockIdx.x >> 4;        // pair slot 0..7
    const int c = blockIdx.x & 15;        // slice 0..15
    const int cb = c * NCR;
    const int rbA = q * BGR, rbB = (q + 8) * BGR;
    const int K0 = w * KCH;

    // W k-pairs in registers: wp[p] = (W[K0+2p][cb+j], W[K0+2p+1][cb+j])
    ull wp[KCH / 2];
#pragma unroll
    for (int p = 0; p < KCH / 2; ++p) {
        float lo = Whh[(size_t)(K0 + 2 * p)     * HID + cb + j];
        float hi = Whh[(size_t)(K0 + 2 * p + 1) * HID + cb + j];
        wp[p] = pk(lo, hi);
    }

    // Staging lane map: f4 indices j and j+32; idx -> (row, seg).
    const int r0 = j >> 3, s0 = j & 7;         // idx j   : rows 0..3
    const int r1 = r0 + 4, s1 = s0;            // idx j+32: rows 4..7
    float* const sWA = sHtA + w * SHT_W;
    float* const sWB = sHtB + w * SHT_W;
    const int sm0 = r0 * 32 + ((s0 ^ r0) << 2);  // swizzled STS offsets
    const int sm1 = r1 * 32 + ((s1 ^ r1) << 2);
    const size_t g0 = (size_t)r0 * HID + K0 + s0 * 4;  // global f4 offsets
    const size_t g1 = (size_t)r1 * HID + K0 + s1 * 4;

    const size_t rowOffA = (size_t)(rbA + w) * HID + cb + j;  // valid w<8
    const size_t rowOffB = (size_t)(rbB + w) * HID + cb + j;
    int* const flagsA = g_flags + q * FST;
    int* const flagsB = g_flags + (q + 8) * FST;

    float xhA = 0.0f, xhB = 0.0f;
    if (w < 8) {
        xhA = __ldcg(&g_buf[rowOffA]);
        xhB = __ldcg(&g_buf[rowOffB]);
    }

    for (int s = 0; s < SEQ; ++s) {
        float pfA = 0.0f, pfB = 0.0f;
        if (w < 8 && s + 1 < SEQ) {
            pfA = __ldcg(&g_buf[(size_t)(s + 1) * BH + rowOffA]);
            pfB = __ldcg(&g_buf[(size_t)(s + 1) * BH + rowOffB]);
        }

        // ================= chain A =================
        {
            float va = xhA;
            if (s > 0) {
                while (ldacq(&flagsA[s - 1]) < NPROD) { }

                // Per-warp self-stage: own k-chunk, 8 rows (1 KB).
                const float* hb = g_buf + (size_t)(s - 1) * BH
                                + (size_t)rbA * HID;
                float4 v0 = __ldcg((const float4*)(hb + g0));
                float4 v1 = __ldcg((const float4*)(hb + g1));
                *(float4*)&sWA[sm0] = v0;
                *(float4*)&sWA[sm1] = v1;
                __syncwarp();

                // Dot: 8 rows x 1 col over own 32 k (swizzled LDS broadcast).
                ull acc[BGR];
#pragma unroll
                for (int r = 0; r < BGR; ++r) acc[r] = 0;
#pragma unroll
                for (int t = 0; t < 8; ++t) {
#pragma unroll
                    for (int r = 0; r < BGR; ++r) {
                        ulonglong2 h2 = *(const ulonglong2*)
                            &sWA[r * 32 + ((t ^ r) << 2)];
                        acc[r] = fma2(h2.x, wp[2 * t],     acc[r]);
                        acc[r] = fma2(h2.y, wp[2 * t + 1], acc[r]);
                    }
                }
#pragma unroll
                for (int r = 0; r < BGR; ++r) {
                    float lo, hi;
                    upk(acc[r], lo, hi);
                    sRdA[(r * 16 + w) * NCR + j] = lo + hi;
                }
                __syncthreads();           // the ONE barrier of this phase

                if (w < 8) {
                    float sum = 0.0f;
#pragma unroll
                    for (int ww = 0; ww < 16; ++ww)
                        sum += sRdA[(w * 16 + ww) * NCR + j];
                    va += sum;
                }
            }
            if (w < 8) {
                g_buf[(size_t)s * BH + rowOffA] = tanhf(va);
                __syncwarp();
                if (j == 0) red_release(&flagsA[s], 1);
            }
        }

        // ================= chain B =================
        {
            float vb = xhB;
            if (s > 0) {
                while (ldacq(&flagsB[s - 1]) < NPROD) { }

                const float* hb = g_buf + (size_t)(s - 1) * BH
                                + (size_t)rbB * HID;
                float4 v0 = __ldcg((const float4*)(hb + g0));
                float4 v1 = __ldcg((const float4*)(hb + g1));
                *(float4*)&sWB[sm0] = v0;
                *(float4*)&sWB[sm1] = v1;
                __syncwarp();

                ull acc[BGR];
#pragma unroll
                for (int r = 0; r < BGR; ++r) acc[r] = 0;
#pragma unroll
                for (int t = 0; t < 8; ++t) {
#pragma unroll
                    for (int r = 0; r < BGR; ++r) {
                        ulonglong2 h2 = *(const ulonglong2*)
                            &sWB[r * 32 + ((t ^ r) << 2)];
                        acc[r] = fma2(h2.x, wp[2 * t],     acc[r]);
                        acc[r] = fma2(h2.y, wp[2 * t + 1], acc[r]);
                    }
                }
#pragma unroll
                for (int r = 0; r < BGR; ++r) {
                    float lo, hi;
                    upk(acc[r], lo, hi);
                    sRdB[(r * 16 + w) * NCR + j] = lo + hi;
                }
                __syncthreads();

                if (w < 8) {
                    float sum = 0.0f;
#pragma unroll
                    for (int ww = 0; ww < 16; ++ww)
                        sum += sRdB[(w * 16 + ww) * NCR + j];
                    vb += sum;
                }
            }
            if (w < 8) {
                g_buf[(size_t)s * BH + rowOffB] = tanhf(vb);
                __syncwarp();
                if (j == 0) red_release(&flagsB[s], 1);
            }
        }

        xhA = pfA;
        xhB = pfB;
    }
}

// ---------------------------------------------------------------------------
// kernel_launch
// Inputs: x[512,128,256], W_xh[256,512], W_hh[512,512],
//         W_hy[512,128], b_h[512], b_y[128]  -> out[512,128,128] fp32
// ---------------------------------------------------------------------------
extern "C" void kernel_launch(void* const* d_in, const int* in_sizes, int n_in,
                              void* d_out, int out_size) {
    const float* x   = (const float*)d_in[0];
    const float* Wxh = (const float*)d_in[1];
    const float* Whh = (const float*)d_in[2];
    const float* Why = (const float*)d_in[3];
    const float* bh  = (const float*)d_in[4];
    const float* by  = (const float*)d_in[5];
    float* out = (float*)d_out;

    float* buf = nullptr;
    cudaGetSymbolAddress((void**)&buf, g_buf);

    cudaFuncSetAttribute(rnn_recur_kernel,
                         cudaFuncAttributeMaxDynamicSharedMemorySize,
                         REC_SMEM_BYTES);

    // 0) zero flags
    zero_flags_kernel<<<(NG * FST + 255) / 256, 256>>>();

    // 1) xh = x @ W_xh + b_h -> g_buf
    {
        dim3 grid(HID / 64, (SEQ * BATCH) / 128);
        sgemm_bias_kernel<128, 64, 16, 8, 4><<<grid, 256>>>(
            x, Wxh, bh, buf, SEQ * BATCH, HID, INDIM);
    }

    // 2) recurrence (two interleaved chains, per-warp stage/publish)
    rnn_recur_kernel<<<128, 512, REC_SMEM_BYTES>>>(Whh);

    // 3) out = hs @ W_hy + b_y
    {
        dim3 grid(ODIM / 64, (SEQ * BATCH) / 128);
        sgemm_bias_kernel<128, 64, 16, 8, 4><<<grid, 256>>>(
            buf, Why, by, out, SEQ * BATCH, ODIM, HID);
    }
}

// round 12
// speedup vs baseline: 5.6827x; 1.0314x over previous
#include <cuda_runtime.h>
#include <cuda_bf16.h>
#include <math.h>

// Problem dims
#define SEQ    512
#define BATCH  128
#define INDIM  256
#define HID    512
#define ODIM   128
#define BH     (BATCH * HID)

// Recurrence: 16 batch groups of 8 rows; 16 hidden slices of 32 cols.
// 128 CTAs; CTA (q,c) runs TWO interleaved chains: group q (A), q+8 (B).
#define NG     16                   // batch groups (8 rows each)
#define BGR    8                    // rows per group
#define NCR    32                   // cols per slice (= lanes)
#define KCH    32                   // k per warp (16 warps x 32 = 512)
#define NPROD  128                  // producers per group flag: 16 CTAs x 8 warps
#define FST    544                  // per-group flag stride (ints)

__device__ float g_buf[(size_t)SEQ * BATCH * HID];
__device__ int g_flags[NG * FST];

typedef unsigned long long ull;

__device__ __forceinline__ ull fma2(ull a, ull b, ull c) {
    ull d;
    asm("fma.rn.f32x2 %0, %1, %2, %3;" : "=l"(d) : "l"(a), "l"(b), "l"(c));
    return d;
}
__device__ __forceinline__ void upk(ull v, float& x, float& y) {
    asm("mov.b64 {%0,%1}, %2;" : "=f"(x), "=f"(y) : "l"(v));
}
__device__ __forceinline__ ull pk(float x, float y) {
    ull d;
    asm("mov.b64 %0, {%1,%2};" : "=l"(d) : "f"(x), "f"(y));
    return d;
}
__device__ __forceinline__ int ldacq(const int* p) {
    int v;
    asm volatile("ld.acquire.gpu.b32 %0, [%1];" : "=r"(v) : "l"(p));
    return v;
}
__device__ __forceinline__ void red_release(int* p, int v) {
    asm volatile("red.release.gpu.global.add.s32 [%0], %1;" :: "l"(p), "r"(v)
                 : "memory");
}

// ---------------------------------------------------------------------------
__global__ void zero_flags_kernel() {
    int i = blockIdx.x * blockDim.x + threadIdx.x;
    if (i < NG * FST) g_flags[i] = 0;
}

// ---------------------------------------------------------------------------
// Tiled fp32 GEMM with bias: C[M,N] = A[M,K] @ B[K,N] + bias[N]
// ---------------------------------------------------------------------------
template <int BM, int BN, int BK, int TM, int TN>
__global__ void __launch_bounds__(256, 2)
sgemm_bias_kernel(const float* __restrict__ A,
                  const float* __restrict__ B,
                  const float* __restrict__ bias,
                  float* __restrict__ C,
                  int M, int N, int K) {
    __shared__ float sA[BK][BM + 4];
    __shared__ float sB[BK][BN];

    const int tid = threadIdx.x;
    const int tx = tid % (BN / TN);
    const int ty = tid / (BN / TN);
    const int m0 = blockIdx.y * BM;
    const int n0 = blockIdx.x * BN;

    float acc[TM][TN];
#pragma unroll
    for (int i = 0; i < TM; i++)
#pragma unroll
        for (int j = 0; j < TN; j++) acc[i][j] = 0.0f;

    for (int k0 = 0; k0 < K; k0 += BK) {
#pragma unroll
        for (int i = 0; i < (BM * BK) / (256 * 4); ++i) {
            int idx = tid + i * 256;
            int r   = idx / (BK / 4);
            int kq  = (idx % (BK / 4)) * 4;
            float4 v = *(const float4*)&A[(size_t)(m0 + r) * K + k0 + kq];
            sA[kq + 0][r] = v.x;
            sA[kq + 1][r] = v.y;
            sA[kq + 2][r] = v.z;
            sA[kq + 3][r] = v.w;
        }
#pragma unroll
        for (int i = 0; i < (BK * BN) / (256 * 4); ++i) {
            int idx = tid + i * 256;
            int r   = idx / (BN / 4);
            int cq  = (idx % (BN / 4)) * 4;
            *(float4*)&sB[r][cq] =
                *(const float4*)&B[(size_t)(k0 + r) * N + n0 + cq];
        }
        __syncthreads();

#pragma unroll
        for (int kk = 0; kk < BK; ++kk) {
            float ra[TM], rb[TN];
#pragma unroll
            for (int i = 0; i < TM; i++) ra[i] = sA[kk][ty * TM + i];
#pragma unroll
            for (int j = 0; j < TN; j++) rb[j] = sB[kk][tx * TN + j];
#pragma unroll
            for (int i = 0; i < TM; i++)
#pragma unroll
                for (int j = 0; j < TN; j++) acc[i][j] += ra[i] * rb[j];
        }
        __syncthreads();
    }

#pragma unroll
    for (int i = 0; i < TM; i++) {
        int row = m0 + ty * TM + i;
#pragma unroll
        for (int j = 0; j < TN; j++) {
            int col = n0 + tx * TN + j;
            C[(size_t)row * N + col] = acc[i][j] + bias[col];
        }
    }
}

// ---------------------------------------------------------------------------
// Persistent recurrence, two interleaved chains, per-warp stage & publish,
// with CROSS-PHASE STAGE PREFETCH:
//   phase A: STS(prefetched A regs) -> syncwarp -> dot A -> sRd -> bar ->
//            [poll B(s-1); LDG B-block -> regs] -> reduce/tanh/STG/publish A
//   phase B: STS(B regs) -> syncwarp -> dot B -> sRd -> bar ->
//            [poll A(s);  LDG A-block -> regs] -> reduce/tanh/STG/publish B
// The poll+LDG sit post-bar (non-smem ops issue under DEFER_BLOCKING) with
// ~1 phase of slack since the producer's publish, and the LDG latency is
// absorbed by the reduce/publish tail instead of the next phase's head.
// ---------------------------------------------------------------------------
#define SHT_W   256                           // floats per warp region
#define SRD_SZ  (BGR * 16 * NCR)              // 4096 floats
#define REC_SMEM_BYTES ((2 * 16 * SHT_W + 2 * SRD_SZ) * 4)   // 64 KB

__global__ void __launch_bounds__(512, 1)
rnn_recur_kernel(const float* __restrict__ Whh) {
    extern __shared__ float sm[];
    float* sHtA = sm;                          // [16 w][256]
    float* sHtB = sm + 16 * SHT_W;
    float* sRdA = sm + 2 * 16 * SHT_W;         // [8 r][16 ww][32 j]
    float* sRdB = sRdA + SRD_SZ;

    const int tid = threadIdx.x;
    const int w = tid >> 5;               // warp = k-chunk id (row id if w<8)
    const int j = tid & 31;               // lane = column
    const int q = blockIdx.x >> 4;        // pair slot 0..7
    const int c = blockIdx.x & 15;        // slice 0..15
    const int cb = c * NCR;
    const int rbA = q * BGR, rbB = (q + 8) * BGR;
    const int K0 = w * KCH;

    // W k-pairs in registers: wp[p] = (W[K0+2p][cb+j], W[K0+2p+1][cb+j])
    ull wp[KCH / 2];
#pragma unroll
    for (int p = 0; p < KCH / 2; ++p) {
        float lo = Whh[(size_t)(K0 + 2 * p)     * HID + cb + j];
        float hi = Whh[(size_t)(K0 + 2 * p + 1) * HID + cb + j];
        wp[p] = pk(lo, hi);
    }

    // Staging lane map: f4 indices j and j+32; idx -> (row, seg).
    const int r0 = j >> 3, s0 = j & 7;         // idx j   : rows 0..3
    const int r1 = r0 + 4, s1 = s0;            // idx j+32: rows 4..7
    float* const sWA = sHtA + w * SHT_W;
    float* const sWB = sHtB + w * SHT_W;
    const int sm0 = r0 * 32 + ((s0 ^ r0) << 2);  // swizzled STS offsets
    const int sm1 = r1 * 32 + ((s1 ^ r1) << 2);
    const size_t g0 = (size_t)r0 * HID + K0 + s0 * 4;  // global f4 offsets
    const size_t g1 = (size_t)r1 * HID + K0 + s1 * 4;

    const size_t rowOffA = (size_t)(rbA + w) * HID + cb + j;  // valid w<8
    const size_t rowOffB = (size_t)(rbB + w) * HID + cb + j;
    int* const flagsA = g_flags + q * FST;
    int* const flagsB = g_flags + (q + 8) * FST;

    float xhA = 0.0f, xhB = 0.0f;
    if (w < 8) {
        xhA = __ldcg(&g_buf[rowOffA]);
        xhB = __ldcg(&g_buf[rowOffB]);
    }

    float4 pA0, pA1, pB0, pB1;    // cross-phase prefetched h blocks

    for (int s = 0; s < SEQ; ++s) {
        float pfA = 0.0f, pfB = 0.0f;
        if (w < 8 && s + 1 < SEQ) {
            pfA = __ldcg(&g_buf[(size_t)(s + 1) * BH + rowOffA]);
            pfB = __ldcg(&g_buf[(size_t)(s + 1) * BH + rowOffB]);
        }

        // ================= phase A =================
        {
            float va = xhA;
            if (s > 0) {
                // Stage from registers prefetched during prev phase B.
                *(float4*)&sWA[sm0] = pA0;
                *(float4*)&sWA[sm1] = pA1;
                __syncwarp();

                ull acc[BGR];
#pragma unroll
                for (int r = 0; r < BGR; ++r) acc[r] = 0;
#pragma unroll
                for (int t = 0; t < 8; ++t) {
#pragma unroll
                    for (int r = 0; r < BGR; ++r) {
                        ulonglong2 h2 = *(const ulonglong2*)
                            &sWA[r * 32 + ((t ^ r) << 2)];
                        acc[r] = fma2(h2.x, wp[2 * t],     acc[r]);
                        acc[r] = fma2(h2.y, wp[2 * t + 1], acc[r]);
                    }
                }
#pragma unroll
                for (int r = 0; r < BGR; ++r) {
                    float lo, hi;
                    upk(acc[r], lo, hi);
                    sRdA[(r * 16 + w) * NCR + j] = lo + hi;
                }
                __syncthreads();

                // Cross-phase prefetch of chain B's block h_B(s-1)
                // (published one full phase ago; poll+LDG overlap the bar
                // drain and the reduce below).
                while (ldacq(&flagsB[s - 1]) < NPROD) { }
                {
                    const float* hb = g_buf + (size_t)(s - 1) * BH
                                    + (size_t)rbB * HID;
                    pB0 = __ldcg((const float4*)(hb + g0));
                    pB1 = __ldcg((const float4*)(hb + g1));
                }

                if (w < 8) {
                    float sum = 0.0f;
#pragma unroll
                    for (int ww = 0; ww < 16; ++ww)
                        sum += sRdA[(w * 16 + ww) * NCR + j];
                    va += sum;
                }
            }
            if (w < 8) {
                g_buf[(size_t)s * BH + rowOffA] = tanhf(va);
                __syncwarp();
                if (j == 0) red_release(&flagsA[s], 1);
            }
        }

        // ================= phase B =================
        {
            float vb = xhB;
            if (s > 0) {
                *(float4*)&sWB[sm0] = pB0;
                *(float4*)&sWB[sm1] = pB1;
                __syncwarp();

                ull acc[BGR];
#pragma unroll
                for (int r = 0; r < BGR; ++r) acc[r] = 0;
#pragma unroll
                for (int t = 0; t < 8; ++t) {
#pragma unroll
                    for (int r = 0; r < BGR; ++r) {
                        ulonglong2 h2 = *(const ulonglong2*)
                            &sWB[r * 32 + ((t ^ r) << 2)];
                        acc[r] = fma2(h2.x, wp[2 * t],     acc[r]);
                        acc[r] = fma2(h2.y, wp[2 * t + 1], acc[r]);
                    }
                }
#pragma unroll
                for (int r = 0; r < BGR; ++r) {
                    float lo, hi;
                    upk(acc[r], lo, hi);
                    sRdB[(r * 16 + w) * NCR + j] = lo + hi;
                }
                __syncthreads();

                // Cross-phase prefetch of chain A's block h_A(s) for the
                // NEXT iteration (published ~one phase ago).
                if (s + 1 < SEQ) {
                    while (ldacq(&flagsA[s]) < NPROD) { }
                    const float* hb = g_buf + (size_t)s * BH
                                    + (size_t)rbA * HID;
                    pA0 = __ldcg((const float4*)(hb + g0));
                    pA1 = __ldcg((const float4*)(hb + g1));
                }

                if (w < 8) {
                    float sum = 0.0f;
#pragma unroll
                    for (int ww = 0; ww < 16; ++ww)
                        sum += sRdB[(w * 16 + ww) * NCR + j];
                    vb += sum;
                }
            } else {
                // s == 0: bootstrap pA = h_A(0) (published in phase A above).
                while (ldacq(&flagsA[0]) < NPROD) { }
                const float* hb = g_buf + (size_t)rbA * HID;
                pA0 = __ldcg((const float4*)(hb + g0));
                pA1 = __ldcg((const float4*)(hb + g1));
            }
            if (w < 8) {
                g_buf[(size_t)s * BH + rowOffB] = tanhf(vb);
                __syncwarp();
                if (j == 0) red_release(&flagsB[s], 1);
            }
        }

        xhA = pfA;
        xhB = pfB;
    }
}

// ---------------------------------------------------------------------------
// kernel_launch
// Inputs: x[512,128,256], W_xh[256,512], W_hh[512,512],
//         W_hy[512,128], b_h[512], b_y[128]  -> out[512,128,128] fp32
// ---------------------------------------------------------------------------
extern "C" void kernel_launch(void* const* d_in, const int* in_sizes, int n_in,
                              void* d_out, int out_size) {
    const float* x   = (const float*)d_in[0];
    const float* Wxh = (const float*)d_in[1];
    const float* Whh = (const float*)d_in[2];
    const float* Why = (const float*)d_in[3];
    const float* bh  = (const float*)d_in[4];
    const float* by  = (const float*)d_in[5];
    float* out = (float*)d_out;

    float* buf = nullptr;
    cudaGetSymbolAddress((void**)&buf, g_buf);

    cudaFuncSetAttribute(rnn_recur_kernel,
                         cudaFuncAttributeMaxDynamicSharedMemorySize,
                         REC_SMEM_BYTES);

    // 0) zero flags
    zero_flags_kernel<<<(NG * FST + 255) / 256, 256>>>();

    // 1) xh = x @ W_xh + b_h -> g_buf   (BK=32: half the barriers of BK=16)
    {
        dim3 grid(HID / 64, (SEQ * BATCH) / 128);
        sgemm_bias_kernel<128, 64, 32, 8, 4><<<grid, 256>>>(
            x, Wxh, bh, buf, SEQ * BATCH, HID, INDIM);
    }

    // 2) recurrence (two interleaved chains, cross-phase stage prefetch)
    rnn_recur_kernel<<<128, 512, REC_SMEM_BYTES>>>(Whh);

    // 3) out = hs @ W_hy + b_y
    {
        dim3 grid(ODIM / 64, (SEQ * BATCH) / 128);
        sgemm_bias_kernel<128, 64, 32, 8, 4><<<grid, 256>>>(
            buf, Why, by, out, SEQ * BATCH, ODIM, HID);
    }
}

// round 13
// speedup vs baseline: 5.9529x; 1.0476x over previous
#include <cuda_runtime.h>
#include <cuda_bf16.h>
#include <math.h>

// Problem dims
#define SEQ    512
#define BATCH  128
#define INDIM  256
#define HID    512
#define ODIM   128
#define BH     (BATCH * HID)

// Recurrence: 16 batch groups of 8 rows; 16 hidden slices of 32 cols.
// 128 CTAs; CTA (q,c) runs TWO interleaved chains: group q (A), q+8 (B).
#define NG     16                   // batch groups (8 rows each)
#define BGR    8                    // rows per group
#define NCR    32                   // cols per slice (= lanes)
#define KCH    32                   // k per warp (16 warps x 32 = 512)
#define NPROD  128                  // producers per group flag: 16 CTAs x 8 warps
#define FST    544                  // per-group flag stride (ints)

__device__ float g_buf[(size_t)SEQ * BATCH * HID];
__device__ int g_flags[NG * FST];

typedef unsigned long long ull;

__device__ __forceinline__ ull fma2(ull a, ull b, ull c) {
    ull d;
    asm("fma.rn.f32x2 %0, %1, %2, %3;" : "=l"(d) : "l"(a), "l"(b), "l"(c));
    return d;
}
__device__ __forceinline__ void upk(ull v, float& x, float& y) {
    asm("mov.b64 {%0,%1}, %2;" : "=f"(x), "=f"(y) : "l"(v));
}
__device__ __forceinline__ ull pk(float x, float y) {
    ull d;
    asm("mov.b64 %0, {%1,%2};" : "=l"(d) : "f"(x), "f"(y));
    return d;
}
__device__ __forceinline__ int ldacq(const int* p) {
    int v;
    asm volatile("ld.acquire.gpu.b32 %0, [%1];" : "=r"(v) : "l"(p));
    return v;
}
__device__ __forceinline__ void red_release(int* p, int v) {
    asm volatile("red.release.gpu.global.add.s32 [%0], %1;" :: "l"(p), "r"(v)
                 : "memory");
}

// ---------------------------------------------------------------------------
__global__ void zero_flags_kernel() {
    int i = blockIdx.x * blockDim.x + threadIdx.x;
    if (i < NG * FST) g_flags[i] = 0;
}

// ---------------------------------------------------------------------------
// Tiled fp32 GEMM with bias: C[M,N] = A[M,K] @ B[K,N] + bias[N]
// (BK=16 shape: measured best at 206us for the xh pass.)
// ---------------------------------------------------------------------------
template <int BM, int BN, int BK, int TM, int TN>
__global__ void __launch_bounds__(256, 2)
sgemm_bias_kernel(const float* __restrict__ A,
                  const float* __restrict__ B,
                  const float* __restrict__ bias,
                  float* __restrict__ C,
                  int M, int N, int K) {
    __shared__ float sA[BK][BM + 4];
    __shared__ float sB[BK][BN];

    const int tid = threadIdx.x;
    const int tx = tid % (BN / TN);
    const int ty = tid / (BN / TN);
    const int m0 = blockIdx.y * BM;
    const int n0 = blockIdx.x * BN;

    float acc[TM][TN];
#pragma unroll
    for (int i = 0; i < TM; i++)
#pragma unroll
        for (int j = 0; j < TN; j++) acc[i][j] = 0.0f;

    for (int k0 = 0; k0 < K; k0 += BK) {
#pragma unroll
        for (int i = 0; i < (BM * BK) / (256 * 4); ++i) {
            int idx = tid + i * 256;
            int r   = idx / (BK / 4);
            int kq  = (idx % (BK / 4)) * 4;
            float4 v = *(const float4*)&A[(size_t)(m0 + r) * K + k0 + kq];
            sA[kq + 0][r] = v.x;
            sA[kq + 1][r] = v.y;
            sA[kq + 2][r] = v.z;
            sA[kq + 3][r] = v.w;
        }
#pragma unroll
        for (int i = 0; i < (BK * BN) / (256 * 4); ++i) {
            int idx = tid + i * 256;
            int r   = idx / (BN / 4);
            int cq  = (idx % (BN / 4)) * 4;
            *(float4*)&sB[r][cq] =
                *(const float4*)&B[(size_t)(k0 + r) * N + n0 + cq];
        }
        __syncthreads();

#pragma unroll
        for (int kk = 0; kk < BK; ++kk) {
            float ra[TM], rb[TN];
#pragma unroll
            for (int i = 0; i < TM; i++) ra[i] = sA[kk][ty * TM + i];
#pragma unroll
            for (int j = 0; j < TN; j++) rb[j] = sB[kk][tx * TN + j];
#pragma unroll
            for (int i = 0; i < TM; i++)
#pragma unroll
                for (int j = 0; j < TN; j++) acc[i][j] += ra[i] * rb[j];
        }
        __syncthreads();
    }

#pragma unroll
    for (int i = 0; i < TM; i++) {
        int row = m0 + ty * TM + i;
#pragma unroll
        for (int j = 0; j < TN; j++) {
            int col = n0 + tx * TN + j;
            C[(size_t)row * N + col] = acc[i][j] + bias[col];
        }
    }
}

// ---------------------------------------------------------------------------
// Persistent recurrence, two interleaved chains, per-warp stage & publish,
// cross-phase stage prefetch HOISTED to post-dot:
//   phase A: STS(pA regs) -> syncwarp -> dot A ->
//            [poll B(s-1); LDG pB]  <-- overlaps sRd/bar/reduce/publish
//            -> sRd -> bar -> reduce/tanh/STG/publish A
//   phase B: symmetric; prefetches pA for the next iteration.
// The poll targets a flag published one full phase (~2000 cyc) earlier, so
// it nearly always passes on the first ld.acquire; the subsequent LDG has
// ~700-900 cyc of shadow before the next phase's STS consumes the regs.
// ---------------------------------------------------------------------------
#define SHT_W   256                           // floats per warp region
#define SRD_SZ  (BGR * 16 * NCR)              // 4096 floats
#define REC_SMEM_BYTES ((2 * 16 * SHT_W + 2 * SRD_SZ) * 4)   // 64 KB

__global__ void __launch_bounds__(512, 1)
rnn_recur_kernel(const float* __restrict__ Whh) {
    extern __shared__ float sm[];
    float* sHtA = sm;                          // [16 w][256]
    float* sHtB = sm + 16 * SHT_W;
    float* sRdA = sm + 2 * 16 * SHT_W;         // [8 r][16 ww][32 j]
    float* sRdB = sRdA + SRD_SZ;

    const int tid = threadIdx.x;
    const int w = tid >> 5;               // warp = k-chunk id (row id if w<8)
    const int j = tid & 31;               // lane = column
    const int q = blockIdx.x >> 4;        // pair slot 0..7
    const int c = blockIdx.x & 15;        // slice 0..15
    const int cb = c * NCR;
    const int rbA = q * BGR, rbB = (q + 8) * BGR;
    const int K0 = w * KCH;

    // W k-pairs in registers: wp[p] = (W[K0+2p][cb+j], W[K0+2p+1][cb+j])
    ull wp[KCH / 2];
#pragma unroll
    for (int p = 0; p < KCH / 2; ++p) {
        float lo = Whh[(size_t)(K0 + 2 * p)     * HID + cb + j];
        float hi = Whh[(size_t)(K0 + 2 * p + 1) * HID + cb + j];
        wp[p] = pk(lo, hi);
    }

    // Staging lane map: f4 indices j and j+32; idx -> (row, seg).
    const int r0 = j >> 3, s0 = j & 7;         // idx j   : rows 0..3
    const int r1 = r0 + 4, s1 = s0;            // idx j+32: rows 4..7
    float* const sWA = sHtA + w * SHT_W;
    float* const sWB = sHtB + w * SHT_W;
    const int sm0 = r0 * 32 + ((s0 ^ r0) << 2);  // swizzled STS offsets
    const int sm1 = r1 * 32 + ((s1 ^ r1) << 2);
    const size_t g0 = (size_t)r0 * HID + K0 + s0 * 4;  // global f4 offsets
    const size_t g1 = (size_t)r1 * HID + K0 + s1 * 4;

    const size_t rowOffA = (size_t)(rbA + w) * HID + cb + j;  // valid w<8
    const size_t rowOffB = (size_t)(rbB + w) * HID + cb + j;
    int* const flagsA = g_flags + q * FST;
    int* const flagsB = g_flags + (q + 8) * FST;

    float xhA = 0.0f, xhB = 0.0f;
    if (w < 8) {
        xhA = __ldcg(&g_buf[rowOffA]);
        xhB = __ldcg(&g_buf[rowOffB]);
    }

    float4 pA0, pA1, pB0, pB1;    // cross-phase prefetched h blocks

    for (int s = 0; s < SEQ; ++s) {
        float pfA = 0.0f, pfB = 0.0f;
        if (w < 8 && s + 1 < SEQ) {
            pfA = __ldcg(&g_buf[(size_t)(s + 1) * BH + rowOffA]);
            pfB = __ldcg(&g_buf[(size_t)(s + 1) * BH + rowOffB]);
        }

        // ================= phase A =================
        {
            float va = xhA;
            if (s > 0) {
                // Stage from registers prefetched during prev phase B.
                *(float4*)&sWA[sm0] = pA0;
                *(float4*)&sWA[sm1] = pA1;
                __syncwarp();

                ull acc[BGR];
#pragma unroll
                for (int r = 0; r < BGR; ++r) acc[r] = 0;
#pragma unroll
                for (int t = 0; t < 8; ++t) {
#pragma unroll
                    for (int r = 0; r < BGR; ++r) {
                        ulonglong2 h2 = *(const ulonglong2*)
                            &sWA[r * 32 + ((t ^ r) << 2)];
                        acc[r] = fma2(h2.x, wp[2 * t],     acc[r]);
                        acc[r] = fma2(h2.y, wp[2 * t + 1], acc[r]);
                    }
                }

                // Hoisted cross-phase prefetch of chain B's h_B(s-1):
                // published one full phase ago; LDG latency overlaps the
                // sRd stores, barrier, reduce and publish below.
                while (ldacq(&flagsB[s - 1]) < NPROD) { }
                {
                    const float* hb = g_buf + (size_t)(s - 1) * BH
                                    + (size_t)rbB * HID;
                    pB0 = __ldcg((const float4*)(hb + g0));
                    pB1 = __ldcg((const float4*)(hb + g1));
                }

#pragma unroll
                for (int r = 0; r < BGR; ++r) {
                    float lo, hi;
                    upk(acc[r], lo, hi);
                    sRdA[(r * 16 + w) * NCR + j] = lo + hi;
                }
                __syncthreads();

                if (w < 8) {
                    float sum = 0.0f;
#pragma unroll
                    for (int ww = 0; ww < 16; ++ww)
                        sum += sRdA[(w * 16 + ww) * NCR + j];
                    va += sum;
                }
            }
            if (w < 8) {
                g_buf[(size_t)s * BH + rowOffA] = tanhf(va);
                __syncwarp();
                if (j == 0) red_release(&flagsA[s], 1);
            }
        }

        // ================= phase B =================
        {
            float vb = xhB;
            if (s > 0) {
                *(float4*)&sWB[sm0] = pB0;
                *(float4*)&sWB[sm1] = pB1;
                __syncwarp();

                ull acc[BGR];
#pragma unroll
                for (int r = 0; r < BGR; ++r) acc[r] = 0;
#pragma unroll
                for (int t = 0; t < 8; ++t) {
#pragma unroll
                    for (int r = 0; r < BGR; ++r) {
                        ulonglong2 h2 = *(const ulonglong2*)
                            &sWB[r * 32 + ((t ^ r) << 2)];
                        acc[r] = fma2(h2.x, wp[2 * t],     acc[r]);
                        acc[r] = fma2(h2.y, wp[2 * t + 1], acc[r]);
                    }
                }

                // Hoisted prefetch of chain A's h_A(s) for next iteration.
                if (s + 1 < SEQ) {
                    while (ldacq(&flagsA[s]) < NPROD) { }
                    const float* hb = g_buf + (size_t)s * BH
                                    + (size_t)rbA * HID;
                    pA0 = __ldcg((const float4*)(hb + g0));
                    pA1 = __ldcg((const float4*)(hb + g1));
                }

#pragma unroll
                for (int r = 0; r < BGR; ++r) {
                    float lo, hi;
                    upk(acc[r], lo, hi);
                    sRdB[(r * 16 + w) * NCR + j] = lo + hi;
                }
                __syncthreads();

                if (w < 8) {
                    float sum = 0.0f;
#pragma unroll
                    for (int ww = 0; ww < 16; ++ww)
                        sum += sRdB[(w * 16 + ww) * NCR + j];
                    vb += sum;
                }
            } else {
                // s == 0: bootstrap pA = h_A(0) (published in phase A above).
                while (ldacq(&flagsA[0]) < NPROD) { }
                const float* hb = g_buf + (size_t)rbA * HID;
                pA0 = __ldcg((const float4*)(hb + g0));
                pA1 = __ldcg((const float4*)(hb + g1));
            }
            if (w < 8) {
                g_buf[(size_t)s * BH + rowOffB] = tanhf(vb);
                __syncwarp();
                if (j == 0) red_release(&flagsB[s], 1);
            }
        }

        xhA = pfA;
        xhB = pfB;
    }
}

// ---------------------------------------------------------------------------
// kernel_launch
// Inputs: x[512,128,256], W_xh[256,512], W_hh[512,512],
//         W_hy[512,128], b_h[512], b_y[128]  -> out[512,128,128] fp32
// ---------------------------------------------------------------------------
extern "C" void kernel_launch(void* const* d_in, const int* in_sizes, int n_in,
                              void* d_out, int out_size) {
    const float* x   = (const float*)d_in[0];
    const float* Wxh = (const float*)d_in[1];
    const float* Whh = (const float*)d_in[2];
    const float* Why = (const float*)d_in[3];
    const float* bh  = (const float*)d_in[4];
    const float* by  = (const float*)d_in[5];
    float* out = (float*)d_out;

    float* buf = nullptr;
    cudaGetSymbolAddress((void**)&buf, g_buf);

    cudaFuncSetAttribute(rnn_recur_kernel,
                         cudaFuncAttributeMaxDynamicSharedMemorySize,
                         REC_SMEM_BYTES);

    // 0) zero flags
    zero_flags_kernel<<<(NG * FST + 255) / 256, 256>>>();

    // 1) xh = x @ W_xh + b_h -> g_buf   (BK=16: measured-best shape)
    {
        dim3 grid(HID / 64, (SEQ * BATCH) / 128);
        sgemm_bias_kernel<128, 64, 16, 8, 4><<<grid, 256>>>(
            x, Wxh, bh, buf, SEQ * BATCH, HID, INDIM);
    }

    // 2) recurrence (two interleaved chains, hoisted cross-phase prefetch)
    rnn_recur_kernel<<<128, 512, REC_SMEM_BYTES>>>(Whh);

    // 3) out = hs @ W_hy + b_y
    {
        dim3 grid(ODIM / 64, (SEQ * BATCH) / 128);
        sgemm_bias_kernel<128, 64, 16, 8, 4><<<grid, 256>>>(
            buf, Why, by, out, SEQ * BATCH, ODIM, HID);
    }
}